// round 12
// baseline (speedup 1.0000x reference)
#include <cuda_runtime.h>
#include <mma.h>
#include <stdint.h>
using namespace nvcuda;

#define BTOT 65536
#define LDZS 272
#define LDWS 48
#define LDC 132
#define CHKB 12288

__device__ float g_loss;
// 72 chunks x 12288B ([hi 128xLDWS | lo], s8, k=32). A:0..7, W0:8..39, W1:40..71
__device__ __align__(16) unsigned char g_wblob[72 * CHKB];
__device__ float g_wscale[1280];  // col scales, tile-order: A 0..255, W0 256..767, W1 768..1279

#define OFF_ZL  17408
#define OFF_WB  34816
#define OFF_CO  59392
#define OFF_RED 93184
#define OFF_XR  95232
#define OFF_STM 97280
#define OFF_STS 97792
#define OFF_STB 98304
#define OFF_WSC 98816
#define OFF_SL  99328
#define SMEM_BYTES 99344

static __device__ __forceinline__ uint32_t smem_u32(const void* p) {
    uint32_t a;
    asm("{ .reg .u64 t; cvta.to.shared.u64 t, %1; cvt.u32.u64 %0, t; }" : "=r"(a) : "l"(p));
    return a;
}
__device__ __forceinline__ float warp_sum(float v) {
#pragma unroll
    for (int o = 16; o; o >>= 1) v += __shfl_xor_sync(0xffffffffu, v, o);
    return v;
}
__device__ __forceinline__ int warp_sum_i(int v) {
#pragma unroll
    for (int o = 16; o; o >>= 1) v += __shfl_xor_sync(0xffffffffu, v, o);
    return v;
}
__device__ __forceinline__ float warp_max(float v) {
#pragma unroll
    for (int o = 16; o; o >>= 1) v = fmaxf(v, __shfl_xor_sync(0xffffffffu, v, o));
    return v;
}
#define CLUSTER_SYNC() do { \
    asm volatile("barrier.cluster.arrive.aligned;" ::: "memory"); \
    asm volatile("barrier.cluster.wait.aligned;" ::: "memory"); } while (0)

// block-wide max; uses red[64..71]; includes leading barrier semantics
__device__ __forceinline__ float block_max(float v, float* red, int tid) {
    v = warp_max(v);
    if ((tid & 31) == 0) red[64 + (tid >> 5)] = v;
    __syncthreads();
    float m = red[64];
#pragma unroll
    for (int i = 1; i < 8; i++) m = fmaxf(m, red[64 + i]);
    __syncthreads();
    return fmaxf(m, 1e-30f);
}

typedef wmma::fragment<wmma::accumulator, 16, 16, 16, int> IAcc;
typedef wmma::fragment<wmma::matrix_a, 16, 16, 16, signed char, wmma::row_major> AFrag;
typedef wmma::fragment<wmma::matrix_b, 16, 16, 16, signed char, wmma::col_major> BFrag;

// one warp per output column: scale + s8 hi/lo quantize into chunked blob
__global__ void convert_w_kernel(const float* __restrict__ Wa,
                                 const float* __restrict__ W0,
                                 const float* __restrict__ W1) {
    int gw = (blockIdx.x * 256 + threadIdx.x) >> 5, lane = threadIdx.x & 31;
    if (blockIdx.x == 0 && threadIdx.x == 0) g_loss = 0.f;
    if (gw >= 1280) return;
    const float* W; int K, gcol, cbase, n;
    if (gw < 256) {
        int tile = gw >> 7; n = gw & 127;
        W = Wa; K = 128; gcol = tile * 128 + n; cbase = tile * 4;
    } else if (gw < 768) {
        int t2 = gw - 256; int tile = t2 >> 7; n = t2 & 127;
        W = W0; K = 256; gcol = (n < 64) ? tile * 64 + n : 256 + tile * 64 + n - 64;
        cbase = 8 + tile * 8;
    } else {
        int t2 = gw - 768; int tile = t2 >> 7; n = t2 & 127;
        W = W1; K = 256; gcol = (n < 64) ? tile * 64 + n : 256 + tile * 64 + n - 64;
        cbase = 40 + tile * 8;
    }
    const float* wr = W + (size_t)gcol * K;
    float mx = 0.f;
    for (int k = lane; k < K; k += 32) mx = fmaxf(mx, fabsf(wr[k]));
    mx = warp_max(mx);
    if (mx == 0.f) mx = 1.f;
    if (lane == 0) g_wscale[gw] = mx;
    float f = 127.f / mx;
    for (int k = lane; k < K; k += 32) {
        float q = wr[k] * f;
        int h = __float2int_rn(q);
        int l = __float2int_rn((q - (float)h) * 254.f);
        unsigned char* dst = g_wblob + (size_t)(cbase + (k >> 5)) * CHKB + n * LDWS + (k & 31);
        dst[0] = (unsigned char)h;
        dst[6144] = (unsigned char)l;
    }
}

__device__ __forceinline__ void cp_chunk(uint32_t dst, const unsigned char* src, int tid) {
#pragma unroll
    for (int t = 0; t < 3; t++) {
        int o = (tid + t * 256) * 16;
        asm volatile("cp.async.cg.shared.global [%0], [%1], 16;" :: "r"(dst + o), "l"(src + o));
    }
    asm volatile("cp.async.commit_group;" ::: "memory");
}

__device__ __forceinline__ void mma_chunk(IAcc a1[2][2], IAcc a2[2][2],
                                          const signed char* Zh, const signed char* Zl,
                                          const signed char* Wb, int wrow, int wcol) {
    const signed char* Whi = Wb;
    const signed char* Wlo = Wb + 6144;
#pragma unroll
    for (int k8 = 0; k8 < 2; k8++) {
        AFrag ah[2], al[2];
        BFrag bh[2], bl[2];
#pragma unroll
        for (int i = 0; i < 2; i++) {
            wmma::load_matrix_sync(ah[i], Zh + (wrow * 32 + i * 16) * LDZS + k8 * 16, LDZS);
            wmma::load_matrix_sync(al[i], Zl + (wrow * 32 + i * 16) * LDZS + k8 * 16, LDZS);
        }
#pragma unroll
        for (int j = 0; j < 2; j++) {
            wmma::load_matrix_sync(bh[j], Whi + (wcol * 32 + j * 16) * LDWS + k8 * 16, LDWS);
            wmma::load_matrix_sync(bl[j], Wlo + (wcol * 32 + j * 16) * LDWS + k8 * 16, LDWS);
        }
#pragma unroll
        for (int i = 0; i < 2; i++)
#pragma unroll
            for (int j = 0; j < 2; j++) {
                wmma::mma_sync(a1[i][j], ah[i], bh[j], a1[i][j]);
                wmma::mma_sync(a2[i][j], ah[i], bl[j], a2[i][j]);
                wmma::mma_sync(a2[i][j], al[i], bh[j], a2[i][j]);
            }
    }
}

template <int KC>
__device__ __forceinline__ void mma_tile(IAcc a1[2][2], IAcc a2[2][2],
                                         const unsigned char* blob,
                                         const signed char* Zh, const signed char* Zl,
                                         char* sm, uint32_t wb32, int tid, int wrow, int wcol) {
    __syncthreads();
    cp_chunk(wb32, blob, tid);
#pragma unroll 1
    for (int kc = 0; kc < KC; kc++) {
        asm volatile("cp.async.wait_group 0;" ::: "memory");
        __syncthreads();
        if (kc + 1 < KC)
            cp_chunk(wb32 + ((kc + 1) & 1) * CHKB, blob + (size_t)(kc + 1) * CHKB, tid);
        mma_chunk(a1, a2, Zh + kc * 32, Zl + kc * 32,
                  (const signed char*)(sm + OFF_WB + (kc & 1) * CHKB), wrow, wcol);
    }
    __syncthreads();
}

// combine a1*254+a2 and store int C
__device__ __forceinline__ void dump_acc(IAcc a1[2][2], IAcc a2[2][2], int* Ci,
                                         int wrow, int wcol) {
#pragma unroll
    for (int i = 0; i < 2; i++)
#pragma unroll
        for (int j = 0; j < 2; j++) {
#pragma unroll
            for (int e = 0; e < a1[i][j].num_elements; e++)
                a1[i][j].x[e] = a1[i][j].x[e] * 254 + a2[i][j].x[e];
            wmma::store_matrix_sync(Ci + (wrow * 32 + i * 16) * LDC + wcol * 32 + j * 16,
                                    a1[i][j], LDC, wmma::mem_row_major);
        }
}

// cluster ghost-BN stats (real units). Loads wsc first. slot must alternate.
__device__ __forceinline__ void stats_cluster(float* red, float* xr, float* stm,
                                              float* sts, float* stb, float* wsc,
                                              const float* __restrict__ g,
                                              const float* __restrict__ bt,
                                              int g0, int g1, const int* Ci,
                                              int wbase, float sfac,
                                              int tid, uint32_t xr32, uint32_t prank, int slot) {
    if (tid < 128) wsc[tid] = g_wscale[wbase + tid] * sfac;
    __syncthreads();
    int col = tid & 127, seg = tid >> 7;
    float s = 0.f, q = 0.f;
    for (int r = seg * 32; r < seg * 32 + 32; r++) {
        float v = (float)Ci[r * LDC + col] * wsc[col];
        s += v;
        q = fmaf(v, v, q);
    }
    red[seg * 128 + col] = s;
    red[256 + seg * 128 + col] = q;
    __syncthreads();
    if (tid < 128) {
        xr[slot * 256 + tid]       = red[tid] + red[128 + tid];
        xr[slot * 256 + 128 + tid] = red[256 + tid] + red[384 + tid];
    }
    __syncthreads();
    CLUSTER_SYNC();
    if (tid < 128) {
        uint32_t pa, pa2;
        asm("mapa.shared::cluster.u32 %0, %1, %2;"
            : "=r"(pa)  : "r"(xr32 + slot * 1024 + tid * 4), "r"(prank));
        asm("mapa.shared::cluster.u32 %0, %1, %2;"
            : "=r"(pa2) : "r"(xr32 + slot * 1024 + 512 + tid * 4), "r"(prank));
        float ps, pq;
        asm("ld.shared::cluster.f32 %0, [%1];" : "=f"(ps) : "r"(pa));
        asm("ld.shared::cluster.f32 %0, [%1];" : "=f"(pq) : "r"(pa2));
        float m = (xr[slot * 256 + tid] + ps) * (1.f / 128.f);
        float var = fmaxf((xr[slot * 256 + 128 + tid] + pq) * (1.f / 128.f) - m * m, 0.f);
        int gc = (tid < 64) ? (g0 + tid) : (g1 + tid - 64);
        stm[tid] = m;
        sts[tid] = g[gc] * rsqrtf(var + 1e-5f);
        stb[tid] = bt[gc];
    }
    __syncthreads();
}

__device__ __forceinline__ void qz4(signed char* Zh, signed char* Zl, int r, int k0,
                                    float4 v, float f127) {
    float f0 = v.x * f127, f1 = v.y * f127, f2 = v.z * f127, f3 = v.w * f127;
    int h0 = __float2int_rn(f0), h1 = __float2int_rn(f1);
    int h2 = __float2int_rn(f2), h3 = __float2int_rn(f3);
    int l0 = __float2int_rn((f0 - (float)h0) * 254.f);
    int l1 = __float2int_rn((f1 - (float)h1) * 254.f);
    int l2 = __float2int_rn((f2 - (float)h2) * 254.f);
    int l3 = __float2int_rn((f3 - (float)h3) * 254.f);
    unsigned hp = (h0 & 255) | ((h1 & 255) << 8) | ((h2 & 255) << 16) | ((h3 & 255) << 24);
    unsigned lp = (l0 & 255) | ((l1 & 255) << 8) | ((l2 & 255) << 16) | ((l3 & 255) << 24);
    *(unsigned*)(Zh + r * LDZS + k0) = hp;
    *(unsigned*)(Zl + r * LDZS + k0) = lp;
}

// returns new Z scale (0 if FINAL)
template <bool FINAL>
__device__ __forceinline__ float glu_block(char* sm, signed char* Zh, signed char* Zl,
                                           int* Ci, float* red, float* xr, float* stm,
                                           float* sts, float* stb, float* wsc,
                                           const unsigned char* blob, int wbase, float s_in,
                                           const float* __restrict__ g,
                                           const float* __restrict__ bt,
                                           float* __restrict__ out, size_t rowbase,
                                           uint32_t wb32, uint32_t xr32, uint32_t prank,
                                           int tid, int wrow, int wcol) {
    float sfac = s_in * (1.f / 4096766.f);
#pragma unroll 1
    for (int ct = 0; ct < 4; ct++) {
        IAcc a1[2][2], a2[2][2];
#pragma unroll
        for (int i = 0; i < 2; i++)
#pragma unroll
            for (int j = 0; j < 2; j++) {
                wmma::fill_fragment(a1[i][j], 0);
                wmma::fill_fragment(a2[i][j], 0);
            }
        mma_tile<8>(a1, a2, blob + (size_t)ct * 8 * CHKB, Zh, Zl, sm, wb32, tid, wrow, wcol);
        dump_acc(a1, a2, Ci, wrow, wcol);
        __syncthreads();
        stats_cluster(red, xr, stm, sts, stb, wsc, g, bt, ct * 64, 256 + ct * 64, Ci,
                      wbase + ct * 128, sfac, tid, xr32, prank, ct & 1);
#pragma unroll
        for (int t = 0; t < 16; t++) {
            int e = tid + t * 256;
            int r = e >> 6, c = e & 63;
            float n1 = ((float)Ci[r * LDC + c] * wsc[c] - stm[c]) * sts[c] + stb[c];
            float n2 = ((float)Ci[r * LDC + 64 + c] * wsc[64 + c] - stm[64 + c]) * sts[64 + c] + stb[64 + c];
            out[(rowbase + r) * 256 + ct * 64 + c] = n1 * (1.f / (1.f + __expf(-n2)));
        }
    }
    __syncthreads();
    float s127 = s_in * (1.f / 127.f);
    float mx = 0.f;
#pragma unroll
    for (int ct = 0; ct < 4; ct++)
#pragma unroll
        for (int t = 0; t < 8; t++) {
            int e = tid + t * 256;
            int r = e >> 5, cp = (e & 31) * 2;
            int oc = ct * 64 + cp;
            float2 glu = *(const float2*)(out + (rowbase + r) * 256 + oc);
            float zp0 = ((float)Zh[r * LDZS + oc] + (float)Zl[r * LDZS + oc] * (1.f / 254.f)) * s127;
            float zp1 = ((float)Zh[r * LDZS + oc + 1] + (float)Zl[r * LDZS + oc + 1] * (1.f / 254.f)) * s127;
            float za = (zp0 + glu.x) * 0.70710678118654752f;
            float zb = (zp1 + glu.y) * 0.70710678118654752f;
            *(float2*)(out + (rowbase + r) * 256 + oc) = make_float2(za, zb);
            mx = fmaxf(mx, fmaxf(fabsf(za), fabsf(zb)));
        }
    if (FINAL) return 0.f;
    float s = block_max(mx, red, tid);   // barriers inside guard Zh/Zl overwrite
    float f127 = 127.f / s;
#pragma unroll
    for (int t = 0; t < 16; t++) {
        int gi = tid + t * 256;
        int r = gi >> 6, k0 = (gi & 63) * 4;
        float4 v = *(const float4*)(out + (rowbase + r) * 256 + k0);
        qz4(Zh, Zl, r, k0, v, f127);
    }
    __syncthreads();
    return s;
}

__global__ void __launch_bounds__(256, 2) __cluster_dims__(2, 1, 1)
tabnet_step(const float* __restrict__ x, const float* __restrict__ a,
            const float* __restrict__ priors,
            const float* __restrict__ ga, const float* __restrict__ bta,
            const float* __restrict__ g0, const float* __restrict__ bt0,
            const float* __restrict__ g1, const float* __restrict__ bt1,
            float* __restrict__ out) {
    extern __shared__ char sm[];
    signed char* Zh = (signed char*)sm;
    signed char* Zl = (signed char*)(sm + OFF_ZL);
    int*   Ci   = (int*)(sm + OFF_CO);
    float* Cf   = (float*)(sm + OFF_CO);
    float* red  = (float*)(sm + OFF_RED);
    float* xr   = (float*)(sm + OFF_XR);
    float* stm  = (float*)(sm + OFF_STM);
    float* sts  = (float*)(sm + OFF_STS);
    float* stb  = (float*)(sm + OFF_STB);
    float* wsc  = (float*)(sm + OFF_WSC);
    float* sloss = (float*)(sm + OFF_SL);

    const int tid = threadIdx.x;
    const int wid = tid >> 5, lane = tid & 31;
    const int wrow = wid >> 2, wcol = wid & 3;
    const size_t rowbase = (size_t)blockIdx.x * 64;
    const uint32_t smb = smem_u32(sm);
    const uint32_t wb32 = smb + OFF_WB, xr32 = smb + OFF_XR;
    uint32_t rank;
    asm("mov.u32 %0, %%cluster_ctarank;" : "=r"(rank));
    const uint32_t prank = rank ^ 1u;

    if (tid == 0) *sloss = 0.f;

    // quantize 'a' (64x128) to s8 hi/lo
    float mx = 0.f;
#pragma unroll
    for (int t = 0; t < 8; t++) {
        int gi = tid + t * 256;
        int r = gi >> 5, k0 = (gi & 31) * 4;
        float4 v = *(const float4*)(a + (rowbase + r) * 128 + k0);
        mx = fmaxf(mx, fmaxf(fmaxf(fabsf(v.x), fabsf(v.y)), fmaxf(fabsf(v.z), fabsf(v.w))));
    }
    float s_a = block_max(mx, red, tid);
    {
        float f127 = 127.f / s_a;
#pragma unroll
        for (int t = 0; t < 8; t++) {
            int gi = tid + t * 256;
            int r = gi >> 5, k0 = (gi & 31) * 4;
            float4 v = *(const float4*)(a + (rowbase + r) * 128 + k0);
            qz4(Zh, Zl, r, k0, v, f127);
        }
    }

    // Stage A: H = GBN(a @ Wa^T) * priors ; cols0-127 -> out gmem, cols128-255 -> Cf
    float sfacA = s_a * (1.f / 4096766.f);
#pragma unroll 1
    for (int nt = 0; nt < 2; nt++) {
        IAcc a1[2][2], a2[2][2];
#pragma unroll
        for (int i = 0; i < 2; i++)
#pragma unroll
            for (int j = 0; j < 2; j++) {
                wmma::fill_fragment(a1[i][j], 0);
                wmma::fill_fragment(a2[i][j], 0);
            }
        mma_tile<4>(a1, a2, g_wblob + (size_t)nt * 4 * CHKB, Zh, Zl, sm, wb32, tid, wrow, wcol);
        dump_acc(a1, a2, Ci, wrow, wcol);
        __syncthreads();
        stats_cluster(red, xr, stm, sts, stb, wsc, ga, bta, nt * 128, nt * 128 + 64, Ci,
                      nt * 128, sfacA, tid, xr32, prank, nt & 1);
#pragma unroll
        for (int t = 0; t < 32; t++) {
            int e = tid + t * 256;
            int r = e >> 7, c = e & 127;
            float h = ((float)Ci[r * LDC + c] * wsc[c] - stm[c]) * sts[c] + stb[c];
            h *= priors[(rowbase + r) * 256 + nt * 128 + c];
            if (nt == 0) out[(rowbase + r) * 256 + c] = h;
            else         Cf[r * LDC + c] = h;
        }
        __syncthreads();
    }

    // sparsemax (exact Michelot) + entropy loss
    {
        float lacc = 0.f;
        for (int rr = 0; rr < 8; rr++) {
            int r = wid * 8 + rr;
            const size_t grow = (rowbase + r) * 256;
            float v[8];
#pragma unroll
            for (int m = 0; m < 8; m++) {
                int c = m * 32 + lane;
                v[m] = (c < 128) ? out[grow + c] : Cf[r * LDC + c - 128];
            }
            float m0 = v[0];
#pragma unroll
            for (int m = 1; m < 8; m++) m0 = fmaxf(m0, v[m]);
            m0 = warp_max(m0);
#pragma unroll
            for (int m = 0; m < 8; m++) v[m] -= m0;
            unsigned act = 0xffu;
            int cnt = 256;
            float tau = 0.f;
            for (int it = 0; it < 256; it++) {
                float s = 0.f;
#pragma unroll
                for (int m = 0; m < 8; m++)
                    if (act & (1u << m)) s += v[m];
                s = warp_sum(s);
                tau = (s - 1.f) / (float)cnt;
                unsigned na = 0; int nc = 0;
#pragma unroll
                for (int m = 0; m < 8; m++)
                    if (v[m] > tau) { na |= (1u << m); nc++; }
                nc = warp_sum_i(nc);
                if (nc == cnt) break;
                act = na; cnt = nc;
            }
#pragma unroll
            for (int m = 0; m < 8; m++) {
                float mk = fmaxf(v[m] - tau, 0.f);
                int c = m * 32 + lane;
                if (c < 128) out[grow + c] = mk;
                else         Cf[r * LDC + c - 128] = mk;
                lacc = fmaf(mk, __logf(mk + 1e-10f), lacc);
            }
        }
        lacc = warp_sum(lacc);
        if (lane == 0) atomicAdd(sloss, lacc);
    }
    __syncthreads();
    if (tid == 0) atomicAdd(&g_loss, *sloss);

    // z0 = x*mask -> out gmem (fp32), track max
    mx = 0.f;
#pragma unroll
    for (int t = 0; t < 16; t++) {
        int e = tid + t * 256;
        int r = e >> 6, c = (e & 63) * 2;
        float2 mk = *(const float2*)(out + (rowbase + r) * 256 + c);
        float2 xx = *(const float2*)(x + (rowbase + r) * 256 + c);
        float z0 = xx.x * mk.x, z1 = xx.y * mk.y;
        *(float2*)(out + (rowbase + r) * 256 + c) = make_float2(z0, z1);
        mx = fmaxf(mx, fmaxf(fabsf(z0), fabsf(z1)));
    }
#pragma unroll
    for (int t = 0; t < 16; t++) {
        int e = tid + t * 256;
        int r = e >> 6, cp = (e & 63) * 2;
        int c = 128 + cp;
        float2 mk = *(const float2*)(Cf + r * LDC + cp);
        float2 xx = *(const float2*)(x + (rowbase + r) * 256 + c);
        float z0 = xx.x * mk.x, z1 = xx.y * mk.y;
        *(float2*)(out + (rowbase + r) * 256 + c) = make_float2(z0, z1);
        mx = fmaxf(mx, fmaxf(fabsf(z0), fabsf(z1)));
    }
    float s0 = block_max(mx, red, tid);
    {
        float f127 = 127.f / s0;
#pragma unroll
        for (int t = 0; t < 16; t++) {
            int gi = tid + t * 256;
            int r = gi >> 6, k0 = (gi & 63) * 4;
            float4 v = *(const float4*)(out + (rowbase + r) * 256 + k0);
            qz4(Zh, Zl, r, k0, v, f127);
        }
    }
    __syncthreads();

    float s1 = glu_block<false>(sm, Zh, Zl, Ci, red, xr, stm, sts, stb, wsc,
                                g_wblob + 8 * CHKB, 256, s0, g0, bt0, out, rowbase,
                                wb32, xr32, prank, tid, wrow, wcol);
    glu_block<true>(sm, Zh, Zl, Ci, red, xr, stm, sts, stb, wsc,
                    g_wblob + 40 * CHKB, 768, s1, g1, bt1, out, rowbase,
                    wb32, xr32, prank, tid, wrow, wcol);
}

__global__ void finalize_kernel(float* out, int out_size) {
    const int zn = BTOT * 256;
    if (out_size > zn) out[out_size - 1] = -g_loss * (1.f / (float)zn);
}
__global__ void pad_kernel() {}

extern "C" void kernel_launch(void* const* d_in, const int* in_sizes, int n_in,
                              void* d_out, int out_size) {
    const float* x   = (const float*)d_in[0];
    const float* a   = (const float*)d_in[1];
    const float* pr  = (const float*)d_in[2];
    const float* Wa  = (const float*)d_in[3];
    const float* ga  = (const float*)d_in[5];
    const float* bta = (const float*)d_in[6];
    const float* W0  = (const float*)d_in[7];
    const float* g0  = (const float*)d_in[9];
    const float* bt0 = (const float*)d_in[10];
    const float* W1  = (const float*)d_in[11];
    const float* g1  = (const float*)d_in[13];
    const float* bt1 = (const float*)d_in[14];
    float* out = (float*)d_out;

    cudaFuncSetAttribute(tabnet_step, cudaFuncAttributeMaxDynamicSharedMemorySize, SMEM_BYTES);

    convert_w_kernel<<<160, 256>>>(Wa, W0, W1);
    pad_kernel<<<1, 1>>>();
    pad_kernel<<<1, 1>>>();
    tabnet_step<<<1024, 256, SMEM_BYTES>>>(x, a, pr, ga, bta, g0, bt0, g1, bt1, out);
    finalize_kernel<<<1, 1>>>(out, out_size);
}

// round 13
// speedup vs baseline: 2.9433x; 2.9433x over previous
#include <cuda_runtime.h>
#include <cuda_bf16.h>
#include <mma.h>
#include <stdint.h>
using namespace nvcuda;

#define BTOT 65536
#define LDZ 264
#define LDWC 40
#define LDC 132
#define CHKB 20480

__device__ float g_loss;
// 72 chunks x 20480B ([hi 128xLDWC | lo 128xLDWC] bf16, k=32 each)
// A: 0..7 (2 tiles x 4kc), W0: 8..39 (4 tiles x 8kc), W1: 40..71
__device__ __align__(16) unsigned char g_wblob[72 * CHKB];

#define OFF_ZLO 33792
#define OFF_WB  67584
#define OFF_RED 108544
#define OFF_XR  110592
#define OFF_STM 112640
#define OFF_STS 113152
#define OFF_STB 113664
#define OFF_SL  114176
#define SMEM_BYTES 114192

static __device__ __forceinline__ uint32_t smem_u32(const void* p) {
    uint32_t a;
    asm("{ .reg .u64 t; cvta.to.shared.u64 t, %1; cvt.u32.u64 %0, t; }" : "=r"(a) : "l"(p));
    return a;
}
__device__ __forceinline__ float warp_sum(float v) {
#pragma unroll
    for (int o = 16; o; o >>= 1) v += __shfl_xor_sync(0xffffffffu, v, o);
    return v;
}
__device__ __forceinline__ int warp_sum_i(int v) {
#pragma unroll
    for (int o = 16; o; o >>= 1) v += __shfl_xor_sync(0xffffffffu, v, o);
    return v;
}
__device__ __forceinline__ float warp_max(float v) {
#pragma unroll
    for (int o = 16; o; o >>= 1) v = fmaxf(v, __shfl_xor_sync(0xffffffffu, v, o));
    return v;
}
#define CLUSTER_SYNC() do { \
    asm volatile("barrier.cluster.arrive.aligned;" ::: "memory"); \
    asm volatile("barrier.cluster.wait.aligned;" ::: "memory"); } while (0)

typedef wmma::fragment<wmma::accumulator, 16, 16, 16, float> AccFrag;

__global__ void convert_w_kernel(const float* __restrict__ Wa,
                                 const float* __restrict__ W0,
                                 const float* __restrict__ W1) {
    int id = blockIdx.x * 256 + threadIdx.x;
    if (id == 0) g_loss = 0.f;
    if (id >= 294912) return;
    int c = id >> 12, e = id & 4095;
    int n = e >> 5, kk = e & 31;
    const float* W; int K, gcol, k;
    if (c < 8) {
        int ct = c >> 2, kc = c & 3;
        W = Wa; K = 128; gcol = ct * 128 + n; k = kc * 32 + kk;
    } else {
        int cc = c - 8, blk = cc >> 5, t2 = cc & 31;
        int ct = t2 >> 3, kc = t2 & 7;
        W = blk ? W1 : W0; K = 256;
        gcol = (n < 64) ? (ct * 64 + n) : (256 + ct * 64 + (n - 64));
        k = kc * 32 + kk;
    }
    float w = W[(size_t)gcol * K + k];
    __nv_bfloat16 hi = __float2bfloat16(w);
    __nv_bfloat16 lo = __float2bfloat16(w - __bfloat162float(hi));
    unsigned char* dst = g_wblob + (size_t)c * CHKB + (size_t)(n * LDWC + kk) * 2;
    *(__nv_bfloat16*)dst = hi;
    *(__nv_bfloat16*)(dst + 10240) = lo;
}

// producer warp copies its pair's 32-col strip (hi 2560B + lo 2560B)
__device__ __forceinline__ void cp_strip(uint32_t dst, const unsigned char* chunk,
                                         int wcol, int lane) {
    const unsigned char* shi = chunk + wcol * 2560;
    const unsigned char* slo = chunk + 10240 + wcol * 2560;
#pragma unroll
    for (int t = 0; t < 5; t++) {
        int o = (lane + t * 32) * 16;
        asm volatile("cp.async.cg.shared.global [%0], [%1], 16;" :: "r"(dst + o), "l"(shi + o));
        asm volatile("cp.async.cg.shared.global [%0], [%1], 16;" :: "r"(dst + 2560 + o), "l"(slo + o));
    }
    asm volatile("cp.async.commit_group;" ::: "memory");
}

// one k=32 chunk, warp tile 32 rows x 32 cols, 3-pass hi/lo; B from pair strip
__device__ __forceinline__ void mma_chunk(AccFrag acc[2][2],
                                          const __nv_bfloat16* Zhi, const __nv_bfloat16* Zlo,
                                          const __nv_bfloat16* Shi, int wrow) {
    const __nv_bfloat16* Slo = Shi + 1280;
#pragma unroll
    for (int k8 = 0; k8 < 2; k8++) {
        wmma::fragment<wmma::matrix_a, 16, 16, 16, __nv_bfloat16, wmma::row_major> ah[2], al[2];
        wmma::fragment<wmma::matrix_b, 16, 16, 16, __nv_bfloat16, wmma::col_major> bh[2], bl[2];
#pragma unroll
        for (int i = 0; i < 2; i++) {
            wmma::load_matrix_sync(ah[i], Zhi + (wrow * 32 + i * 16) * LDZ + k8 * 16, LDZ);
            wmma::load_matrix_sync(al[i], Zlo + (wrow * 32 + i * 16) * LDZ + k8 * 16, LDZ);
        }
#pragma unroll
        for (int j = 0; j < 2; j++) {
            wmma::load_matrix_sync(bh[j], Shi + (j * 16) * LDWC + k8 * 16, LDWC);
            wmma::load_matrix_sync(bl[j], Slo + (j * 16) * LDWC + k8 * 16, LDWC);
        }
#pragma unroll
        for (int i = 0; i < 2; i++)
#pragma unroll
            for (int j = 0; j < 2; j++) wmma::mma_sync(acc[i][j], ah[i], bh[j], acc[i][j]);
#pragma unroll
        for (int i = 0; i < 2; i++)
#pragma unroll
            for (int j = 0; j < 2; j++) wmma::mma_sync(acc[i][j], ah[i], bl[j], acc[i][j]);
#pragma unroll
        for (int i = 0; i < 2; i++)
#pragma unroll
            for (int j = 0; j < 2; j++) wmma::mma_sync(acc[i][j], al[i], bh[j], acc[i][j]);
    }
}

// KC chunks; per-pair double-buffered strips; only pair barriers in the loop
template <int KC>
__device__ __forceinline__ void mma_tile(AccFrag acc[2][2], const unsigned char* blob,
                                         const __nv_bfloat16* Zhi, const __nv_bfloat16* Zlo,
                                         char* sm, uint32_t smb,
                                         int lane, int wrow, int wcol) {
    __syncthreads();                       // strip/Cout region free
    const bool isP = (wrow == 0);
    const uint32_t pb32 = smb + OFF_WB + wcol * 10240;
    const __nv_bfloat16* strips = (const __nv_bfloat16*)(sm + OFF_WB + wcol * 10240);
    if (isP) cp_strip(pb32, blob, wcol, lane);
    const int barid = 1 + wcol;
#pragma unroll 1
    for (int kc = 0; kc < KC; kc++) {
        if (isP) asm volatile("cp.async.wait_group 0;" ::: "memory");
        asm volatile("bar.sync %0, 64;" :: "r"(barid) : "memory");
        if (isP && kc + 1 < KC)
            cp_strip(pb32 + ((kc + 1) & 1) * 5120, blob + (size_t)(kc + 1) * CHKB, wcol, lane);
        mma_chunk(acc, Zhi + kc * 32, Zlo + kc * 32, strips + (kc & 1) * 2560, wrow);
    }
    __syncthreads();                       // all mma done before Cout overwrite
}

__device__ __forceinline__ void dump_acc(AccFrag acc[2][2], float* Cout, int wrow, int wcol) {
#pragma unroll
    for (int i = 0; i < 2; i++)
#pragma unroll
        for (int j = 0; j < 2; j++)
            wmma::store_matrix_sync(Cout + (wrow * 32 + i * 16) * LDC + wcol * 32 + j * 16,
                                    acc[i][j], LDC, wmma::mem_row_major);
}

// ghost-BN stats over 128 rows split across the 2-CTA cluster; slot must alternate
__device__ __forceinline__ void stats_cluster(float* red, float* xr, float* stm,
                                              float* sts, float* stb,
                                              const float* __restrict__ g,
                                              const float* __restrict__ bt,
                                              int g0, int g1, const float* Cout,
                                              int tid, uint32_t xr32, uint32_t prank,
                                              int slot) {
    int col = tid & 127, seg = tid >> 7;
    float s = 0.f, q = 0.f;
    for (int r = seg * 32; r < seg * 32 + 32; r++) {
        float v = Cout[r * LDC + col];
        s += v;
        q = fmaf(v, v, q);
    }
    red[seg * 128 + col] = s;
    red[256 + seg * 128 + col] = q;
    __syncthreads();
    if (tid < 128) {
        xr[slot * 256 + tid]       = red[tid] + red[128 + tid];
        xr[slot * 256 + 128 + tid] = red[256 + tid] + red[384 + tid];
    }
    __syncthreads();
    CLUSTER_SYNC();
    if (tid < 128) {
        uint32_t pa, pa2;
        asm("mapa.shared::cluster.u32 %0, %1, %2;"
            : "=r"(pa)  : "r"(xr32 + slot * 1024 + tid * 4), "r"(prank));
        asm("mapa.shared::cluster.u32 %0, %1, %2;"
            : "=r"(pa2) : "r"(xr32 + slot * 1024 + 512 + tid * 4), "r"(prank));
        float ps, pq;
        asm("ld.shared::cluster.f32 %0, [%1];" : "=f"(ps) : "r"(pa));
        asm("ld.shared::cluster.f32 %0, [%1];" : "=f"(pq) : "r"(pa2));
        float m = (xr[slot * 256 + tid] + ps) * (1.f / 128.f);
        float var = fmaxf((xr[slot * 256 + 128 + tid] + pq) * (1.f / 128.f) - m * m, 0.f);
        int gc = (tid < 64) ? (g0 + tid) : (g1 + tid - 64);
        stm[tid] = m;
        sts[tid] = g[gc] * rsqrtf(var + 1e-5f);
        stb[tid] = bt[gc];
    }
    __syncthreads();
}

template <bool FINAL>
__device__ __forceinline__ void glu_block(char* sm, __nv_bfloat16* Zhi, __nv_bfloat16* Zlo,
                                          float* Cout, float* red, float* xr,
                                          float* stm, float* sts, float* stb,
                                          const unsigned char* blob,
                                          const float* __restrict__ g,
                                          const float* __restrict__ bt,
                                          float* __restrict__ out, size_t rowbase,
                                          uint32_t smb, uint32_t xr32, uint32_t prank,
                                          int tid, int lane, int wrow, int wcol) {
#pragma unroll 1
    for (int ct = 0; ct < 4; ct++) {
        AccFrag acc[2][2];
#pragma unroll
        for (int i = 0; i < 2; i++)
#pragma unroll
            for (int j = 0; j < 2; j++) wmma::fill_fragment(acc[i][j], 0.f);
        mma_tile<8>(acc, blob + (size_t)ct * 8 * CHKB, Zhi, Zlo, sm, smb, lane, wrow, wcol);
        dump_acc(acc, Cout, wrow, wcol);
        __syncthreads();
        stats_cluster(red, xr, stm, sts, stb, g, bt, ct * 64, 256 + ct * 64, Cout,
                      tid, xr32, prank, ct & 1);
#pragma unroll
        for (int t = 0; t < 16; t++) {
            int e = tid + t * 256;
            int r = e >> 6, c = e & 63;
            float n1 = (Cout[r * LDC + c] - stm[c]) * sts[c] + stb[c];
            float n2 = (Cout[r * LDC + 64 + c] - stm[64 + c]) * sts[64 + c] + stb[64 + c];
            out[(rowbase + r) * 256 + ct * 64 + c] = n1 * (1.f / (1.f + __expf(-n2)));
        }
    }
    __syncthreads();
#pragma unroll
    for (int ct = 0; ct < 4; ct++)
#pragma unroll
        for (int t = 0; t < 8; t++) {
            int e = tid + t * 256;
            int r = e >> 5, cp = (e & 31) * 2;
            int oc = ct * 64 + cp;
            float2 glu = *(const float2*)(out + (rowbase + r) * 256 + oc);
            __nv_bfloat162 zh = *(__nv_bfloat162*)(Zhi + r * LDZ + oc);
            __nv_bfloat162 zl = *(__nv_bfloat162*)(Zlo + r * LDZ + oc);
            float za = (__bfloat162float(zh.x) + __bfloat162float(zl.x) + glu.x) * 0.70710678118654752f;
            float zb = (__bfloat162float(zh.y) + __bfloat162float(zl.y) + glu.y) * 0.70710678118654752f;
            if (FINAL) {
                *(float2*)(out + (rowbase + r) * 256 + oc) = make_float2(za, zb);
            } else {
                __nv_bfloat16 ha = __float2bfloat16(za), hb = __float2bfloat16(zb);
                *(__nv_bfloat162*)(Zhi + r * LDZ + oc) = __halves2bfloat162(ha, hb);
                *(__nv_bfloat162*)(Zlo + r * LDZ + oc) = __halves2bfloat162(
                    __float2bfloat16(za - __bfloat162float(ha)),
                    __float2bfloat16(zb - __bfloat162float(hb)));
            }
        }
    if (!FINAL) __syncthreads();
}

__global__ void __launch_bounds__(256, 2) __cluster_dims__(2, 1, 1)
tabnet_step(const float* __restrict__ x, const float* __restrict__ a,
            const float* __restrict__ priors,
            const float* __restrict__ ga, const float* __restrict__ bta,
            const float* __restrict__ g0, const float* __restrict__ bt0,
            const float* __restrict__ g1, const float* __restrict__ bt1,
            float* __restrict__ out) {
    extern __shared__ char sm[];
    __nv_bfloat16* Zhi = (__nv_bfloat16*)sm;
    __nv_bfloat16* Zlo = (__nv_bfloat16*)(sm + OFF_ZLO);
    float* Cout  = (float*)(sm + OFF_WB);
    float* red   = (float*)(sm + OFF_RED);
    float* xr    = (float*)(sm + OFF_XR);
    float* stm   = (float*)(sm + OFF_STM);
    float* sts   = (float*)(sm + OFF_STS);
    float* stb   = (float*)(sm + OFF_STB);
    float* sloss = (float*)(sm + OFF_SL);

    const int tid = threadIdx.x;
    const int wid = tid >> 5, lane = tid & 31;
    const int wrow = wid >> 2, wcol = wid & 3;
    const size_t rowbase = (size_t)blockIdx.x * 64;
    const uint32_t smb = smem_u32(sm);
    const uint32_t xr32 = smb + OFF_XR;
    uint32_t rank;
    asm("mov.u32 %0, %%cluster_ctarank;" : "=r"(rank));
    const uint32_t prank = rank ^ 1u;

    if (tid == 0) *sloss = 0.f;

    // a (64x128 fp32) -> bf16 hi/lo operand
#pragma unroll
    for (int s = 0; s < 4; s++) {
        int gi = tid + s * 256;
        int r = gi >> 4, k0 = (gi & 15) * 8;
        const float* ap = a + (rowbase + r) * 128 + k0;
        float4 f0 = *(const float4*)ap;
        float4 f1 = *(const float4*)(ap + 4);
        float v[8] = {f0.x, f0.y, f0.z, f0.w, f1.x, f1.y, f1.z, f1.w};
        union { __nv_bfloat16 h[8]; uint4 u; } Hh, Hl;
#pragma unroll
        for (int j = 0; j < 8; j++) {
            __nv_bfloat16 hb = __float2bfloat16(v[j]);
            Hh.h[j] = hb;
            Hl.h[j] = __float2bfloat16(v[j] - __bfloat162float(hb));
        }
        *(uint4*)(Zhi + r * LDZ + k0) = Hh.u;
        *(uint4*)(Zlo + r * LDZ + k0) = Hl.u;
    }

    // Stage A: H = GBN(a @ Wa^T) * priors ; cols0-127 parked in out gmem
#pragma unroll 1
    for (int nt = 0; nt < 2; nt++) {
        AccFrag acc[2][2];
#pragma unroll
        for (int i = 0; i < 2; i++)
#pragma unroll
            for (int j = 0; j < 2; j++) wmma::fill_fragment(acc[i][j], 0.f);
        mma_tile<4>(acc, g_wblob + (size_t)nt * 4 * CHKB, Zhi, Zlo, sm, smb, lane, wrow, wcol);
        dump_acc(acc, Cout, wrow, wcol);
        __syncthreads();
        stats_cluster(red, xr, stm, sts, stb, ga, bta, nt * 128, nt * 128 + 64, Cout,
                      tid, xr32, prank, nt & 1);
#pragma unroll
        for (int t = 0; t < 32; t++) {
            int e = tid + t * 256;
            int r = e >> 7, c = e & 127;
            float h = (Cout[r * LDC + c] - stm[c]) * sts[c] + stb[c];
            h *= priors[(rowbase + r) * 256 + nt * 128 + c];
            if (nt == 0) out[(rowbase + r) * 256 + c] = h;
            else         Cout[r * LDC + c] = h;
        }
        __syncthreads();
    }

    // sparsemax (exact Michelot) + entropy loss
    {
        float lacc = 0.f;
        for (int rr = 0; rr < 8; rr++) {
            int r = wid * 8 + rr;
            const size_t grow = (rowbase + r) * 256;
            float v[8];
#pragma unroll
            for (int m = 0; m < 8; m++) {
                int c = m * 32 + lane;
                v[m] = (c < 128) ? out[grow + c] : Cout[r * LDC + c - 128];
            }
            float m0 = v[0];
#pragma unroll
            for (int m = 1; m < 8; m++) m0 = fmaxf(m0, v[m]);
            m0 = warp_max(m0);
#pragma unroll
            for (int m = 0; m < 8; m++) v[m] -= m0;
            unsigned act = 0xffu;
            int cnt = 256;
            float tau = 0.f;
            for (int it = 0; it < 256; it++) {
                float s = 0.f;
#pragma unroll
                for (int m = 0; m < 8; m++)
                    if (act & (1u << m)) s += v[m];
                s = warp_sum(s);
                tau = (s - 1.f) / (float)cnt;
                unsigned na = 0; int nc = 0;
#pragma unroll
                for (int m = 0; m < 8; m++)
                    if (v[m] > tau) { na |= (1u << m); nc++; }
                nc = warp_sum_i(nc);
                if (nc == cnt) break;
                act = na; cnt = nc;
            }
#pragma unroll
            for (int m = 0; m < 8; m++) {
                float mk = fmaxf(v[m] - tau, 0.f);
                int c = m * 32 + lane;
                if (c < 128) out[grow + c] = mk;
                else         Cout[r * LDC + c - 128] = mk;
                lacc = fmaf(mk, __logf(mk + 1e-10f), lacc);
            }
        }
        lacc = warp_sum(lacc);
        if (lane == 0) atomicAdd(sloss, lacc);
    }
    __syncthreads();
    if (tid == 0) atomicAdd(&g_loss, *sloss);

    // Z = x * mask -> bf16 hi/lo
#pragma unroll
    for (int t = 0; t < 16; t++) {
        int e = tid + t * 256;
        int r = e >> 6, c = (e & 63) * 2;
        float2 mk = *(const float2*)(out + (rowbase + r) * 256 + c);
        float2 xx = *(const float2*)(x + (rowbase + r) * 256 + c);
        float z0 = xx.x * mk.x, z1 = xx.y * mk.y;
        __nv_bfloat16 h0 = __float2bfloat16(z0), h1 = __float2bfloat16(z1);
        *(__nv_bfloat162*)(Zhi + r * LDZ + c) = __halves2bfloat162(h0, h1);
        *(__nv_bfloat162*)(Zlo + r * LDZ + c) = __halves2bfloat162(
            __float2bfloat16(z0 - __bfloat162float(h0)),
            __float2bfloat16(z1 - __bfloat162float(h1)));
    }
#pragma unroll
    for (int t = 0; t < 16; t++) {
        int e = tid + t * 256;
        int r = e >> 6, cp = (e & 63) * 2;
        int c = 128 + cp;
        float2 mk = *(const float2*)(Cout + r * LDC + cp);
        float2 xx = *(const float2*)(x + (rowbase + r) * 256 + c);
        float z0 = xx.x * mk.x, z1 = xx.y * mk.y;
        __nv_bfloat16 h0 = __float2bfloat16(z0), h1 = __float2bfloat16(z1);
        *(__nv_bfloat162*)(Zhi + r * LDZ + c) = __halves2bfloat162(h0, h1);
        *(__nv_bfloat162*)(Zlo + r * LDZ + c) = __halves2bfloat162(
            __float2bfloat16(z0 - __bfloat162float(h0)),
            __float2bfloat16(z1 - __bfloat162float(h1)));
    }
    __syncthreads();

    glu_block<false>(sm, Zhi, Zlo, Cout, red, xr, stm, sts, stb,
                     g_wblob + 8 * CHKB, g0, bt0, out, rowbase,
                     smb, xr32, prank, tid, lane, wrow, wcol);
    glu_block<true>(sm, Zhi, Zlo, Cout, red, xr, stm, sts, stb,
                    g_wblob + 40 * CHKB, g1, bt1, out, rowbase,
                    smb, xr32, prank, tid, lane, wrow, wcol);
}

__global__ void finalize_kernel(float* out, int out_size) {
    const int zn = BTOT * 256;
    if (out_size > zn) out[out_size - 1] = -g_loss * (1.f / (float)zn);
}
__global__ void pad_kernel() {}

extern "C" void kernel_launch(void* const* d_in, const int* in_sizes, int n_in,
                              void* d_out, int out_size) {
    const float* x   = (const float*)d_in[0];
    const float* a   = (const float*)d_in[1];
    const float* pr  = (const float*)d_in[2];
    const float* Wa  = (const float*)d_in[3];
    const float* ga  = (const float*)d_in[5];
    const float* bta = (const float*)d_in[6];
    const float* W0  = (const float*)d_in[7];
    const float* g0  = (const float*)d_in[9];
    const float* bt0 = (const float*)d_in[10];
    const float* W1  = (const float*)d_in[11];
    const float* g1  = (const float*)d_in[13];
    const float* bt1 = (const float*)d_in[14];
    float* out = (float*)d_out;

    cudaFuncSetAttribute(tabnet_step, cudaFuncAttributeMaxDynamicSharedMemorySize, SMEM_BYTES);

    convert_w_kernel<<<1152, 256>>>(Wa, W0, W1);
    pad_kernel<<<1, 1>>>();
    pad_kernel<<<1, 1>>>();
    tabnet_step<<<1024, 256, SMEM_BYTES>>>(x, a, pr, ga, bta, g0, bt0, g1, bt1, out);
    finalize_kernel<<<1, 1>>>(out, out_size);
}